// round 9
// baseline (speedup 1.0000x reference)
#include <cuda_runtime.h>
#include <cuda_fp16.h>
#include <float.h>
#include <math.h>

#define CCH 128
#define HWF 409600   // 640*640
#define WF 640
#define HF 640
#define NTPB (HWF / 32)   // 12800 transpose blocks (32 pixels each)

// Slot permutation: slot s holds channel c(s) = (s&3)*32 + (s>>2)
// Mp[c*128 + s] = M[c(s)][c]  (fp32, slot-major columns), up[s] = u[c(s)]
__device__ __align__(16) float d_Mp[CCH * CCH];
__device__ __align__(16) float d_up[CCH];
// Transposed f1 in fp16: [H*W][128 slots]
__device__ __align__(16) __half d_f1t[(size_t)HWF * CCH];

// packed fp32x2 FMA (Blackwell)
#define FMA_F32X2(d, a, b, c) \
    asm("fma.rn.f32x2 %0, %1, %2, %3;" : "=l"(d) : "l"(a), "l"(b), "l"(c))

__device__ __forceinline__ unsigned long long pack_f32x2(float lo, float hi) {
    unsigned long long r;
    unsigned ulo = __float_as_uint(lo), uhi = __float_as_uint(hi);
    asm("mov.b64 %0, {%1, %2};" : "=l"(r) : "r"(ulo), "r"(uhi));
    return r;
}
__device__ __forceinline__ void unpack_f32x2(unsigned long long v, float& lo, float& hi) {
    unsigned ulo, uhi;
    asm("mov.b64 {%0, %1}, %2;" : "=r"(ulo), "=r"(uhi) : "l"(v));
    lo = __uint_as_float(ulo);
    hi = __uint_as_float(uhi);
}

// ---------------------------------------------------------------------------
// Kernel A: blocks [0,NTPB): transpose f1 -> d_f1t (fp16, slot layout).
//           blocks [NTPB, NTPB+128): precompute Mp (slot-permuted) and up.
__global__ void __launch_bounds__(256)
transpose_f1(const float* __restrict__ f1,
             const float* __restrict__ W, const float* __restrict__ b)
{
    __shared__ float wcol[CCH];
    const int blk = blockIdx.x;
    const int t = threadIdx.x;
    const int w = t >> 5, l = t & 31;

    if (blk >= NTPB) {
        // ---- precompute role: row o of M = W^T W -> permuted column s(o) ----
        const int o = blk - NTPB;
        if (t < CCH) wcol[t] = W[t * CCH + o];
        __syncthreads();
        if (t < CCH) {
            float acc = 0.f;
#pragma unroll 8
            for (int k = 0; k < CCH; k++) acc += wcol[k] * W[k * CCH + t];
            const int so = 4 * (o & 31) + (o >> 5);
            d_Mp[t * CCH + so] = acc;      // Mp[c=t][s(o)] = M[o][t] (symmetric)
            if (t == 0) {
                float uu = 0.f;
                for (int k = 0; k < CCH; k++) uu += wcol[k] * b[k];
                d_up[so] = uu;
            }
        }
        return;
    }

    // ---- transpose role: 32 pixels per block; lane = pixel, warp = 16 slots ----
    const int p = blk * 32 + l;     // this lane's pixel
    float v[16];                    // slot s = 16w + d holds channel 4w+(d>>2)+32(d&3)
#pragma unroll
    for (int d = 0; d < 16; d++) {
        const int c = 4 * w + (d >> 2) + 32 * (d & 3);
        v[d] = __ldg(f1 + (size_t)c * HWF + p);
    }
    unsigned q[8];
#pragma unroll
    for (int d = 0; d < 8; d++) {
        __half2 h = __floats2half2_rn(v[2 * d], v[2 * d + 1]);
        q[d] = *reinterpret_cast<unsigned*>(&h);
    }
    __half* dst = d_f1t + (size_t)p * CCH + 16 * w;
    *reinterpret_cast<uint4*>(dst)     = make_uint4(q[0], q[1], q[2], q[3]);
    *reinterpret_cast<uint4*>(dst + 8) = make_uint4(q[4], q[5], q[6], q[7]);
}

// ---------------------------------------------------------------------------
// Kernel B (fused): one warp per point. Stage Mp in smem; gather r0; compute
// g = Mp*r0 + up (slot space) with FFMA2; 5x5 patch correlation from fp16 f1t;
// warp softmax + expectation; write pts0/pts1.
// smem: Mp float[16384] @0 (65536), r0s float[8*128] @65536 (4096) = 69632 B
#define CORR_SMEM 69632
__global__ void __launch_bounds__(256)
corr_fused(const float* __restrict__ mk0, const float* __restrict__ mk1,
           const float* __restrict__ f0, const int* __restrict__ stride_ptr,
           float* __restrict__ out, int N)
{
    extern __shared__ char smraw[];
    float* Mp  = (float*)smraw;
    float* r0s = (float*)(smraw + 65536);

    const int t = threadIdx.x;
    const int wid = t >> 5, lane = t & 31;

    {   // stage Mp: 4096 uint4 across 256 threads
        const uint4* src = (const uint4*)d_Mp;
        uint4* dstv = (uint4*)Mp;
#pragma unroll
        for (int i = 0; i < 16; i++) dstv[i * 256 + t] = __ldg(&src[i * 256 + t]);
    }
    __syncthreads();

    const int n = blockIdx.x * 8 + wid;
    if (n >= N) return;

    const int stride = stride_ptr ? __ldg(stride_ptr) : 8;
    const int fr = stride >> 1;
    const float scalef = (float)(stride / fr);
    const float halfstr = (float)(stride >> 1);

    const float m0x = __ldg(&mk0[2 * n]), m0y = __ldg(&mk0[2 * n + 1]);
    const float m1x = __ldg(&mk1[2 * n]), m1y = __ldg(&mk1[2 * n + 1]);
    const int cx0 = (int)(m0x * (float)fr), cy0 = (int)(m0y * (float)fr);
    const int cx1 = (int)(m1x * (float)fr), cy1 = (int)(m1y * (float)fr);
    const bool valid = cx0 >= 2 && cx0 + 2 < WF && cy0 >= 2 && cy0 + 2 < HF &&
                       cx1 >= 2 && cx1 + 2 < WF && cy1 >= 2 && cy1 + 2 < HF;
    const int cx0c = min(max(cx0, 2), WF - 3), cy0c = min(max(cy0, 2), HF - 3);
    const int cx1c = min(max(cx1, 2), WF - 3), cy1c = min(max(cy1, 2), HF - 3);
    const int pix0 = cy0c * WF + cx0c;
    const size_t pixb = (size_t)cy1c * WF + cx1c;

    // gather r0: lane loads channels {lane, lane+32, lane+64, lane+96}
    {
        float* r0w = &r0s[wid * CCH];
#pragma unroll
        for (int k = 0; k < 4; k++) {
            const int c = lane + 32 * k;
            r0w[c] = __ldg(f0 + (size_t)c * HWF + pix0);
        }
    }
    __syncwarp();

    // matvec: g[4l..4l+3] = up + sum_c Mp[c][4l..4l+3] * r0[c]
    float4 g4;
    {
        const float4 u4 = *(const float4*)&d_up[4 * lane];
        unsigned long long a01 = pack_f32x2(u4.x, u4.y);
        unsigned long long a23 = pack_f32x2(u4.z, u4.w);
        const float* r0w = &r0s[wid * CCH];
#pragma unroll 4
        for (int c = 0; c < CCH; c++) {
            const unsigned long long* mrow =
                (const unsigned long long*)&Mp[c * CCH + 4 * lane];
            const float rc = r0w[c];
            const unsigned long long rr = pack_f32x2(rc, rc);
            FMA_F32X2(a01, mrow[0], rr, a01);
            FMA_F32X2(a23, mrow[1], rr, a23);
        }
        unpack_f32x2(a01, g4.x, g4.y);
        unpack_f32x2(a23, g4.z, g4.w);
    }

    // 5x5 patch correlation
    float corr = -FLT_MAX;   // lane p (p<25) ends up holding corr[p]
#pragma unroll
    for (int row = 0; row < 5; row++) {
        const size_t rb = (pixb + (size_t)(row - 2) * WF - 2) * CCH + lane * 4;
        float r[5];
#pragma unroll
        for (int col = 0; col < 5; col++) {
            uint2 u = __ldg((const uint2*)(d_f1t + rb + (size_t)col * CCH));
            __half2 h0 = *reinterpret_cast<__half2*>(&u.x);
            __half2 h1 = *reinterpret_cast<__half2*>(&u.y);
            float2 f01 = __half22float2(h0);
            float2 f23 = __half22float2(h1);
            r[col] = g4.x * f01.x + g4.y * f01.y + g4.z * f23.x + g4.w * f23.y;
        }
#pragma unroll
        for (int d = 16; d; d >>= 1) {
            r[0] += __shfl_xor_sync(0xffffffffu, r[0], d);
            r[1] += __shfl_xor_sync(0xffffffffu, r[1], d);
            r[2] += __shfl_xor_sync(0xffffffffu, r[2], d);
            r[3] += __shfl_xor_sync(0xffffffffu, r[3], d);
            r[4] += __shfl_xor_sync(0xffffffffu, r[4], d);
        }
        const int p0 = row * 5;
#pragma unroll
        for (int col = 0; col < 5; col++)
            if (lane == p0 + col) corr = r[col];
    }

    // softmax over lanes 0..24 + expectation (per-point constant cancels)
    const bool inpatch = lane < 25;
    const int dx = lane % 5 - 2;
    const int dy = lane / 5 - 2;
    float cm = corr;
#pragma unroll
    for (int d = 16; d; d >>= 1)
        cm = fmaxf(cm, __shfl_xor_sync(0xffffffffu, cm, d));
    float e  = inpatch ? __expf(corr - cm) : 0.f;
    float ex = e * (float)dx;
    float ey = e * (float)dy;
    float s  = e;
#pragma unroll
    for (int d = 16; d; d >>= 1) {
        s  += __shfl_xor_sync(0xffffffffu, s,  d);
        ex += __shfl_xor_sync(0xffffffffu, ex, d);
        ey += __shfl_xor_sync(0xffffffffu, ey, d);
    }
    if (lane == 0) {
        out[2 * n]     = m0x * (float)stride + halfstr;
        out[2 * n + 1] = m0y * (float)stride + halfstr;
        const float inv = scalef / s;
        const float ox = valid ? ex * inv : 0.f;
        const float oy = valid ? ey * inv : 0.f;
        out[2 * N + 2 * n]     = m1x * (float)stride + halfstr + ox;
        out[2 * N + 2 * n + 1] = m1y * (float)stride + halfstr + oy;
    }
}

// ---------------------------------------------------------------------------
extern "C" void kernel_launch(void* const* d_in, const int* in_sizes, int n_in,
                              void* d_out, int out_size) {
    const float* mk0 = (const float*)d_in[0];
    const float* mk1 = (const float*)d_in[1];
    const float* f0  = (const float*)d_in[2];
    const float* f1  = (const float*)d_in[3];
    const float* pw  = (const float*)d_in[4];
    const float* pb  = (const float*)d_in[5];
    const int* stridep = (n_in >= 7) ? (const int*)d_in[6] : nullptr;
    float* out = (float*)d_out;

    int N = in_sizes[0] / 2;

    transpose_f1<<<NTPB + 128, 256>>>(f1, pw, pb);

    cudaFuncSetAttribute(corr_fused,
                         cudaFuncAttributeMaxDynamicSharedMemorySize, CORR_SMEM);
    corr_fused<<<(N + 7) / 8, 256, CORR_SMEM>>>(mk0, mk1, f0, stridep, out, N);
}

// round 10
// speedup vs baseline: 1.2017x; 1.2017x over previous
#include <cuda_runtime.h>
#include <cuda_fp16.h>
#include <float.h>
#include <math.h>

#define CCH 128
#define HWF 409600   // 640*640
#define WF 640
#define HF 640
#define NTPB (HWF / 32)   // 12800 transpose blocks (32 pixels each)
#define PPB 48            // points per g-block

// Precomputed M = W^T W (fp32, symmetric), u = W^T b
__device__ __align__(16) float d_M[CCH * CCH];
__device__ __align__(16) float d_u[CCH];
// Transposed f1 in fp16: [H*W][128 slots]; slot s holds channel c(s) = (s&3)*32 + (s>>2)
__device__ __align__(16) __half d_f1t[(size_t)HWF * CCH];
// g[n] = M * r0[n] + u, stored slot-permuted to match d_f1t
__device__ __align__(16) float d_g[20000 * CCH];

// packed fp32x2 FMA (Blackwell)
#define FMA_F32X2(d, a, b, c) \
    asm("fma.rn.f32x2 %0, %1, %2, %3;" : "=l"(d) : "l"(a), "l"(b), "l"(c))

__device__ __forceinline__ unsigned long long pack_f32x2(float lo, float hi) {
    unsigned long long r;
    unsigned ulo = __float_as_uint(lo), uhi = __float_as_uint(hi);
    asm("mov.b64 %0, {%1, %2};" : "=l"(r) : "r"(ulo), "r"(uhi));
    return r;
}
__device__ __forceinline__ void unpack_f32x2(unsigned long long v, float& lo, float& hi) {
    unsigned ulo, uhi;
    asm("mov.b64 {%0, %1}, %2;" : "=r"(ulo), "=r"(uhi) : "l"(v));
    lo = __uint_as_float(ulo);
    hi = __uint_as_float(uhi);
}

// ---------------------------------------------------------------------------
// Kernel A: blocks [0,NTPB): lane=pixel register transpose f1 -> d_f1t (fp16).
//           blocks [NTPB, NTPB+128): precompute M (fp32) and u.
__global__ void __launch_bounds__(256)
transpose_f1(const float* __restrict__ f1,
             const float* __restrict__ W, const float* __restrict__ b)
{
    __shared__ float wcol[CCH];
    const int blk = blockIdx.x;
    const int t = threadIdx.x;
    const int w = t >> 5, l = t & 31;

    if (blk >= NTPB) {
        // ---- precompute role: row o of M = W^T W, u[o] ----
        const int o = blk - NTPB;
        if (t < CCH) wcol[t] = W[t * CCH + o];
        __syncthreads();
        if (t < CCH) {
            float acc = 0.f;
#pragma unroll 8
            for (int k = 0; k < CCH; k++) acc += wcol[k] * W[k * CCH + t];
            d_M[o * CCH + t] = acc;
            if (t == 0) {
                float uu = 0.f;
                for (int k = 0; k < CCH; k++) uu += wcol[k] * b[k];
                d_u[o] = uu;
            }
        }
        return;
    }

    // ---- transpose role: 32 pixels per block; lane = pixel, warp = 16 slots ----
    const int p = blk * 32 + l;     // this lane's pixel
    float v[16];                    // slot s = 16w + d holds channel 4w+(d>>2)+32(d&3)
#pragma unroll
    for (int d = 0; d < 16; d++) {
        const int c = 4 * w + (d >> 2) + 32 * (d & 3);
        v[d] = __ldg(f1 + (size_t)c * HWF + p);
    }
    unsigned q[8];
#pragma unroll
    for (int d = 0; d < 8; d++) {
        __half2 h = __floats2half2_rn(v[2 * d], v[2 * d + 1]);
        q[d] = *reinterpret_cast<unsigned*>(&h);
    }
    __half* dst = d_f1t + (size_t)p * CCH + 16 * w;
    *reinterpret_cast<uint4*>(dst)     = make_uint4(q[0], q[1], q[2], q[3]);
    *reinterpret_cast<uint4*>(dst + 8) = make_uint4(q[4], q[5], q[6], q[7]);
}

// ---------------------------------------------------------------------------
// Kernel B: g[n] = M * r0[n] + u. PPB points per block, ONE gather phase.
// smem bytes: Msh float[16384]    @0      (65536)
//             r0p float[128*50]   @65536  (25600)  pitch 50: 8B-aligned u64 rows
//             ush float[128]      @91136  (512)
//             hi  int[48]         @91648  (192)
#define R0PITCH 50
#define G_SMEM 91840
__global__ void __launch_bounds__(256)
g_kernel(const float* __restrict__ mk0, const float* __restrict__ f0,
         const int* __restrict__ stride_ptr, int N)
{
    extern __shared__ char smraw[];
    float* Msh = (float*)smraw;
    float* r0p = (float*)(smraw + 65536);
    float* ush = (float*)(smraw + 91136);
    int*   hi  = (int*)(smraw + 91648);

    const int t = threadIdx.x;
    const int stride = stride_ptr ? __ldg(stride_ptr) : 8;
    const int fr = stride >> 1;
    const int n0blk = blockIdx.x * PPB;

    // header: 48 points
    if (t < PPB) {
        int n = n0blk + t;
        int nc = n < N ? n : N - 1;
        float m0x = mk0[2 * nc], m0y = mk0[2 * nc + 1];
        int cx0 = (int)(m0x * (float)fr), cy0 = (int)(m0y * (float)fr);
        int cx0c = min(max(cx0, 2), WF - 3), cy0c = min(max(cy0, 2), HF - 3);
        hi[t] = cy0c * WF + cx0c;
    }
    if (t < CCH) ush[t] = d_u[t];
    __syncthreads();

    const int o    = t & 127;
    const int half = t >> 7;

    {   // stage M (float4) + gather all 48 points' channel-o values (24/thread)
        const uint4* Ms = (const uint4*)d_M;
        uint4* Md = (uint4*)Msh;
#pragma unroll
        for (int i = 0; i < 16; i++) Md[i * 256 + t] = __ldg(&Ms[i * 256 + t]);
        const float* fp = f0 + (size_t)o * HWF;
#pragma unroll
        for (int k = 0; k < 24; k++) {
            const int q = half * 24 + k;
            r0p[o * R0PITCH + q] = __ldg(fp + hi[q]);
        }
    }
    __syncthreads();

    // 3 matvec batches of 16 points; each half-block handles 8 points/batch
    const int s = (o & 31) * 4 + (o >> 5);   // slot for channel o
    const float uo = ush[o];
#pragma unroll
    for (int b = 0; b < 3; b++) {
        unsigned long long a0 = pack_f32x2(uo, uo);
        unsigned long long a1 = a0, a2 = a0, a3 = a0;
        const int qb = b * 16 + half * 8;
#pragma unroll 8
        for (int c = 0; c < CCH; c++) {
            const float m = Msh[c * CCH + o];      // symmetric: M[c][o]==M[o][c]
            const unsigned long long m2 = pack_f32x2(m, m);
            const unsigned long long* rp =
                (const unsigned long long*)&r0p[c * R0PITCH + qb];
            FMA_F32X2(a0, m2, rp[0], a0);
            FMA_F32X2(a1, m2, rp[1], a1);
            FMA_F32X2(a2, m2, rp[2], a2);
            FMA_F32X2(a3, m2, rp[3], a3);
        }
        float g[8];
        unpack_f32x2(a0, g[0], g[1]);
        unpack_f32x2(a1, g[2], g[3]);
        unpack_f32x2(a2, g[4], g[5]);
        unpack_f32x2(a3, g[6], g[7]);
#pragma unroll
        for (int k = 0; k < 8; k++) {
            const int n = n0blk + qb + k;
            if (n < N) d_g[(size_t)n * CCH + s] = g[k];
        }
    }
}

// ---------------------------------------------------------------------------
// Kernel C: one warp per point: correlation (fp16 f1t) + softmax + outputs.
__global__ void __launch_bounds__(256)
corr_kernel(const float* __restrict__ mk0, const float* __restrict__ mk1,
            const int* __restrict__ stride_ptr, float* __restrict__ out, int N)
{
    const int wid = threadIdx.x >> 5, lane = threadIdx.x & 31;
    const int n = blockIdx.x * 8 + wid;
    if (n >= N) return;

    const int stride = stride_ptr ? __ldg(stride_ptr) : 8;
    const int fr = stride >> 1;
    const float scalef = (float)(stride / fr);
    const float halfstr = (float)(stride >> 1);

    const float m0x = __ldg(&mk0[2 * n]), m0y = __ldg(&mk0[2 * n + 1]);
    const float m1x = __ldg(&mk1[2 * n]), m1y = __ldg(&mk1[2 * n + 1]);
    const int cx0 = (int)(m0x * (float)fr), cy0 = (int)(m0y * (float)fr);
    const int cx1 = (int)(m1x * (float)fr), cy1 = (int)(m1y * (float)fr);
    const bool valid = cx0 >= 2 && cx0 + 2 < WF && cy0 >= 2 && cy0 + 2 < HF &&
                       cx1 >= 2 && cx1 + 2 < WF && cy1 >= 2 && cy1 + 2 < HF;
    const int cx1c = min(max(cx1, 2), WF - 3);
    const int cy1c = min(max(cy1, 2), HF - 3);
    const size_t pixb = (size_t)cy1c * WF + cx1c;

    // slots 4*lane..4*lane+3 (d_g written with matching permutation)
    const float4 g4 = *(const float4*)&d_g[(size_t)n * CCH + lane * 4];

    float corr = -FLT_MAX;   // lane p (p<25) ends up holding corr[p]
#pragma unroll
    for (int row = 0; row < 5; row++) {
        const size_t rb = (pixb + (size_t)(row - 2) * WF - 2) * CCH + lane * 4;
        float r[5];
#pragma unroll
        for (int col = 0; col < 5; col++) {
            uint2 u = __ldg((const uint2*)(d_f1t + rb + (size_t)col * CCH));
            __half2 h0 = *reinterpret_cast<__half2*>(&u.x);
            __half2 h1 = *reinterpret_cast<__half2*>(&u.y);
            float2 f01 = __half22float2(h0);
            float2 f23 = __half22float2(h1);
            r[col] = g4.x * f01.x + g4.y * f01.y + g4.z * f23.x + g4.w * f23.y;
        }
#pragma unroll
        for (int d = 16; d; d >>= 1) {
            r[0] += __shfl_xor_sync(0xffffffffu, r[0], d);
            r[1] += __shfl_xor_sync(0xffffffffu, r[1], d);
            r[2] += __shfl_xor_sync(0xffffffffu, r[2], d);
            r[3] += __shfl_xor_sync(0xffffffffu, r[3], d);
            r[4] += __shfl_xor_sync(0xffffffffu, r[4], d);
        }
        const int p0 = row * 5;
#pragma unroll
        for (int col = 0; col < 5; col++)
            if (lane == p0 + col) corr = r[col];
    }

    // softmax over lanes 0..24 + expectation (per-point constant cancels)
    const bool inpatch = lane < 25;
    const int dx = lane % 5 - 2;
    const int dy = lane / 5 - 2;
    float cm = corr;
#pragma unroll
    for (int d = 16; d; d >>= 1)
        cm = fmaxf(cm, __shfl_xor_sync(0xffffffffu, cm, d));
    float e  = inpatch ? __expf(corr - cm) : 0.f;
    float ex = e * (float)dx;
    float ey = e * (float)dy;
    float s  = e;
#pragma unroll
    for (int d = 16; d; d >>= 1) {
        s  += __shfl_xor_sync(0xffffffffu, s,  d);
        ex += __shfl_xor_sync(0xffffffffu, ex, d);
        ey += __shfl_xor_sync(0xffffffffu, ey, d);
    }
    if (lane == 0) {
        out[2 * n]     = m0x * (float)stride + halfstr;
        out[2 * n + 1] = m0y * (float)stride + halfstr;
        const float inv = scalef / s;
        const float ox = valid ? ex * inv : 0.f;
        const float oy = valid ? ey * inv : 0.f;
        out[2 * N + 2 * n]     = m1x * (float)stride + halfstr + ox;
        out[2 * N + 2 * n + 1] = m1y * (float)stride + halfstr + oy;
    }
}

// ---------------------------------------------------------------------------
extern "C" void kernel_launch(void* const* d_in, const int* in_sizes, int n_in,
                              void* d_out, int out_size) {
    const float* mk0 = (const float*)d_in[0];
    const float* mk1 = (const float*)d_in[1];
    const float* f0  = (const float*)d_in[2];
    const float* f1  = (const float*)d_in[3];
    const float* pw  = (const float*)d_in[4];
    const float* pb  = (const float*)d_in[5];
    const int* stridep = (n_in >= 7) ? (const int*)d_in[6] : nullptr;
    float* out = (float*)d_out;

    int N = in_sizes[0] / 2;

    transpose_f1<<<NTPB + 128, 256>>>(f1, pw, pb);

    cudaFuncSetAttribute(g_kernel,
                         cudaFuncAttributeMaxDynamicSharedMemorySize, G_SMEM);
    g_kernel<<<(N + PPB - 1) / PPB, 256, G_SMEM>>>(mk0, f0, stridep, N);

    corr_kernel<<<(N + 7) / 8, 256>>>(mk0, mk1, stridep, out, N);
}

// round 11
// speedup vs baseline: 1.3553x; 1.1279x over previous
#include <cuda_runtime.h>
#include <cuda_fp16.h>
#include <float.h>
#include <math.h>

#define CCH 128
#define HWF 409600   // 640*640
#define WF 640
#define HF 640
#define NTPB (HWF / 64)   // 6400 transpose blocks (64 pixels each)
#define PPB 48            // points per g-block

// Precomputed M = W^T W in fp16 (symmetric), u = W^T b fp32
__device__ __align__(16) __half d_Mh[CCH * CCH];
__device__ __align__(16) float  d_u[CCH];
// Transposed f1 in fp16: [H*W][128 slots]; slot s holds channel c(s) = (s&3)*32 + (s>>2)
__device__ __align__(16) __half d_f1t[(size_t)HWF * CCH];
// g[n] = M * r0[n] + u, stored slot-permuted to match d_f1t
__device__ __align__(16) float d_g[20000 * CCH];

// packed fp32x2 FMA (Blackwell)
#define FMA_F32X2(d, a, b, c) \
    asm("fma.rn.f32x2 %0, %1, %2, %3;" : "=l"(d) : "l"(a), "l"(b), "l"(c))

__device__ __forceinline__ unsigned long long pack_f32x2(float lo, float hi) {
    unsigned long long r;
    unsigned ulo = __float_as_uint(lo), uhi = __float_as_uint(hi);
    asm("mov.b64 %0, {%1, %2};" : "=l"(r) : "r"(ulo), "r"(uhi));
    return r;
}
__device__ __forceinline__ void unpack_f32x2(unsigned long long v, float& lo, float& hi) {
    unsigned ulo, uhi;
    asm("mov.b64 {%0, %1}, %2;" : "=r"(ulo), "=r"(uhi) : "l"(v));
    lo = __uint_as_float(ulo);
    hi = __uint_as_float(uhi);
}

// ---------------------------------------------------------------------------
// Kernel A: blocks [0,NTPB): lane=pixel-pair register transpose f1 -> d_f1t.
//           blocks [NTPB, NTPB+128): precompute M (fp16) and u.
__global__ void __launch_bounds__(256)
transpose_f1(const float* __restrict__ f1,
             const float* __restrict__ W, const float* __restrict__ b)
{
    __shared__ float wcol[CCH];
    const int blk = blockIdx.x;
    const int t = threadIdx.x;
    const int w = t >> 5, l = t & 31;

    if (blk >= NTPB) {
        // ---- precompute role: row o of M = W^T W, u[o] ----
        const int o = blk - NTPB;
        if (t < CCH) wcol[t] = W[t * CCH + o];
        __syncthreads();
        if (t < CCH) {
            float acc = 0.f;
#pragma unroll 8
            for (int k = 0; k < CCH; k++) acc += wcol[k] * W[k * CCH + t];
            d_Mh[o * CCH + t] = __float2half(acc);
            if (t == 0) {
                float uu = 0.f;
                for (int k = 0; k < CCH; k++) uu += wcol[k] * b[k];
                d_u[o] = uu;
            }
        }
        return;
    }

    // ---- transpose role: 64 pixels per block; lane = 2 pixels, warp = 16 slots ----
    const int p0 = blk * 64 + 2 * l;   // this lane's pixel pair
    float2 v[16];                      // v[d] = slot 16w+d = channel 4w+(d>>2)+32(d&3)
#pragma unroll
    for (int d = 0; d < 16; d++) {
        const int c = 4 * w + (d >> 2) + 32 * (d & 3);
        v[d] = __ldg((const float2*)(f1 + (size_t)c * HWF + p0));
    }
#pragma unroll
    for (int j2 = 0; j2 < 2; j2++) {
        unsigned q[8];
#pragma unroll
        for (int d = 0; d < 8; d++) {
            const float a = j2 ? v[2 * d].y     : v[2 * d].x;
            const float bq = j2 ? v[2 * d + 1].y : v[2 * d + 1].x;
            __half2 h = __floats2half2_rn(a, bq);
            q[d] = *reinterpret_cast<unsigned*>(&h);
        }
        __half* dst = d_f1t + (size_t)(p0 + j2) * CCH + 16 * w;
        *reinterpret_cast<uint4*>(dst)     = make_uint4(q[0], q[1], q[2], q[3]);
        *reinterpret_cast<uint4*>(dst + 8) = make_uint4(q[4], q[5], q[6], q[7]);
    }
}

// ---------------------------------------------------------------------------
// Kernel B: g[n] = M * r0[n] + u. PPB=48 points/block, ONE gather phase,
// fp16 M in smem (59 KB total -> 3 CTAs/SM -> all 417 blocks in one wave).
// smem bytes: Msh half[16384] @0 (32768)
//             r0p float[128*50] @32768 (25600)   pitch 50: 8B-aligned u64 rows
//             ush float[128]    @58368 (512)
//             hi  int[48]       @58880 (192)
#define R0PITCH 50
#define G_SMEM 59072
__global__ void __launch_bounds__(256, 3)
g_kernel(const float* __restrict__ mk0, const float* __restrict__ f0,
         const int* __restrict__ stride_ptr, int N)
{
    extern __shared__ char smraw[];
    __half* Msh = (__half*)smraw;
    float*  r0p = (float*)(smraw + 32768);
    float*  ush = (float*)(smraw + 58368);
    int*    hi  = (int*)(smraw + 58880);

    const int t = threadIdx.x;
    const int stride = stride_ptr ? __ldg(stride_ptr) : 8;
    const int fr = stride >> 1;
    const int n0blk = blockIdx.x * PPB;

    // header: 48 points
    if (t < PPB) {
        int n = n0blk + t;
        int nc = n < N ? n : N - 1;
        float m0x = mk0[2 * nc], m0y = mk0[2 * nc + 1];
        int cx0 = (int)(m0x * (float)fr), cy0 = (int)(m0y * (float)fr);
        int cx0c = min(max(cx0, 2), WF - 3), cy0c = min(max(cy0, 2), HF - 3);
        hi[t] = cy0c * WF + cx0c;
    }
    if (t < CCH) ush[t] = d_u[t];
    __syncthreads();

    const int o    = t & 127;
    const int half = t >> 7;

    {   // stage fp16 M (uint4) + gather all 48 points' channel-o values (24/thread)
        const uint4* Ms = (const uint4*)d_Mh;
        uint4* Md = (uint4*)Msh;
#pragma unroll
        for (int i = 0; i < 8; i++) Md[i * 256 + t] = __ldg(&Ms[i * 256 + t]);
        const float* fp = f0 + (size_t)o * HWF;
#pragma unroll
        for (int k = 0; k < 24; k++) {
            const int q = half * 24 + k;
            r0p[o * R0PITCH + q] = __ldg(fp + hi[q]);
        }
    }
    __syncthreads();

    // 3 matvec batches of 16 points; each half-block handles 8 points/batch
    const int s = (o & 31) * 4 + (o >> 5);   // slot for channel o
    const float uo = ush[o];
#pragma unroll
    for (int bb = 0; bb < 3; bb++) {
        unsigned long long a0 = pack_f32x2(uo, uo);
        unsigned long long a1 = a0, a2 = a0, a3 = a0;
        const int qb = bb * 16 + half * 8;
#pragma unroll 8
        for (int c = 0; c < CCH; c++) {
            const float m = __half2float(Msh[c * CCH + o]);  // symmetric
            const unsigned long long m2 = pack_f32x2(m, m);
            const unsigned long long* rp =
                (const unsigned long long*)&r0p[c * R0PITCH + qb];
            FMA_F32X2(a0, m2, rp[0], a0);
            FMA_F32X2(a1, m2, rp[1], a1);
            FMA_F32X2(a2, m2, rp[2], a2);
            FMA_F32X2(a3, m2, rp[3], a3);
        }
        float g[8];
        unpack_f32x2(a0, g[0], g[1]);
        unpack_f32x2(a1, g[2], g[3]);
        unpack_f32x2(a2, g[4], g[5]);
        unpack_f32x2(a3, g[6], g[7]);
#pragma unroll
        for (int k = 0; k < 8; k++) {
            const int n = n0blk + qb + k;
            if (n < N) d_g[(size_t)n * CCH + s] = g[k];
        }
    }
}

// ---------------------------------------------------------------------------
// Kernel C: one warp per point: correlation (fp16 f1t) + softmax + outputs.
__global__ void __launch_bounds__(256)
corr_kernel(const float* __restrict__ mk0, const float* __restrict__ mk1,
            const int* __restrict__ stride_ptr, float* __restrict__ out, int N)
{
    const int wid = threadIdx.x >> 5, lane = threadIdx.x & 31;
    const int n = blockIdx.x * 8 + wid;
    if (n >= N) return;

    const int stride = stride_ptr ? __ldg(stride_ptr) : 8;
    const int fr = stride >> 1;
    const float scalef = (float)(stride / fr);
    const float halfstr = (float)(stride >> 1);

    const float m0x = __ldg(&mk0[2 * n]), m0y = __ldg(&mk0[2 * n + 1]);
    const float m1x = __ldg(&mk1[2 * n]), m1y = __ldg(&mk1[2 * n + 1]);
    const int cx0 = (int)(m0x * (float)fr), cy0 = (int)(m0y * (float)fr);
    const int cx1 = (int)(m1x * (float)fr), cy1 = (int)(m1y * (float)fr);
    const bool valid = cx0 >= 2 && cx0 + 2 < WF && cy0 >= 2 && cy0 + 2 < HF &&
                       cx1 >= 2 && cx1 + 2 < WF && cy1 >= 2 && cy1 + 2 < HF;
    const int cx1c = min(max(cx1, 2), WF - 3);
    const int cy1c = min(max(cy1, 2), HF - 3);
    const size_t pixb = (size_t)cy1c * WF + cx1c;

    // slots 4*lane..4*lane+3 (d_g written with matching permutation)
    const float4 g4 = *(const float4*)&d_g[(size_t)n * CCH + lane * 4];

    float corr = -FLT_MAX;   // lane p (p<25) ends up holding corr[p]
#pragma unroll
    for (int row = 0; row < 5; row++) {
        const size_t rb = (pixb + (size_t)(row - 2) * WF - 2) * CCH + lane * 4;
        float r[5];
#pragma unroll
        for (int col = 0; col < 5; col++) {
            uint2 u = __ldg((const uint2*)(d_f1t + rb + (size_t)col * CCH));
            __half2 h0 = *reinterpret_cast<__half2*>(&u.x);
            __half2 h1 = *reinterpret_cast<__half2*>(&u.y);
            float2 f01 = __half22float2(h0);
            float2 f23 = __half22float2(h1);
            r[col] = g4.x * f01.x + g4.y * f01.y + g4.z * f23.x + g4.w * f23.y;
        }
#pragma unroll
        for (int d = 16; d; d >>= 1) {
            r[0] += __shfl_xor_sync(0xffffffffu, r[0], d);
            r[1] += __shfl_xor_sync(0xffffffffu, r[1], d);
            r[2] += __shfl_xor_sync(0xffffffffu, r[2], d);
            r[3] += __shfl_xor_sync(0xffffffffu, r[3], d);
            r[4] += __shfl_xor_sync(0xffffffffu, r[4], d);
        }
        const int p0 = row * 5;
#pragma unroll
        for (int col = 0; col < 5; col++)
            if (lane == p0 + col) corr = r[col];
    }

    // softmax over lanes 0..24 + expectation (per-point constant cancels)
    const bool inpatch = lane < 25;
    const int dx = lane % 5 - 2;
    const int dy = lane / 5 - 2;
    float cm = corr;
#pragma unroll
    for (int d = 16; d; d >>= 1)
        cm = fmaxf(cm, __shfl_xor_sync(0xffffffffu, cm, d));
    float e  = inpatch ? __expf(corr - cm) : 0.f;
    float ex = e * (float)dx;
    float ey = e * (float)dy;
    float s  = e;
#pragma unroll
    for (int d = 16; d; d >>= 1) {
        s  += __shfl_xor_sync(0xffffffffu, s,  d);
        ex += __shfl_xor_sync(0xffffffffu, ex, d);
        ey += __shfl_xor_sync(0xffffffffu, ey, d);
    }
    if (lane == 0) {
        out[2 * n]     = m0x * (float)stride + halfstr;
        out[2 * n + 1] = m0y * (float)stride + halfstr;
        const float inv = scalef / s;
        const float ox = valid ? ex * inv : 0.f;
        const float oy = valid ? ey * inv : 0.f;
        out[2 * N + 2 * n]     = m1x * (float)stride + halfstr + ox;
        out[2 * N + 2 * n + 1] = m1y * (float)stride + halfstr + oy;
    }
}

// ---------------------------------------------------------------------------
extern "C" void kernel_launch(void* const* d_in, const int* in_sizes, int n_in,
                              void* d_out, int out_size) {
    const float* mk0 = (const float*)d_in[0];
    const float* mk1 = (const float*)d_in[1];
    const float* f0  = (const float*)d_in[2];
    const float* f1  = (const float*)d_in[3];
    const float* pw  = (const float*)d_in[4];
    const float* pb  = (const float*)d_in[5];
    const int* stridep = (n_in >= 7) ? (const int*)d_in[6] : nullptr;
    float* out = (float*)d_out;

    int N = in_sizes[0] / 2;

    transpose_f1<<<NTPB + 128, 256>>>(f1, pw, pb);

    cudaFuncSetAttribute(g_kernel,
                         cudaFuncAttributeMaxDynamicSharedMemorySize, G_SMEM);
    g_kernel<<<(N + PPB - 1) / PPB, 256, G_SMEM>>>(mk0, f0, stridep, N);

    corr_kernel<<<(N + 7) / 8, 256>>>(mk0, mk1, stridep, out, N);
}

// round 12
// speedup vs baseline: 1.4221x; 1.0493x over previous
#include <cuda_runtime.h>
#include <cuda_fp16.h>
#include <float.h>
#include <math.h>

#define CCH 128
#define HWF 409600   // 640*640
#define WF 640
#define HF 640
#define NTPB (HWF / 64)   // 6400 transpose blocks (64 pixels each)
#define PPB 48            // points per g-block (3 batches of 16)

// Precomputed M = W^T W in fp16 (symmetric), u = W^T b fp32
__device__ __align__(16) __half d_Mh[CCH * CCH];
__device__ __align__(16) float  d_u[CCH];
// Transposed f1 in fp16: [H*W][128 slots]; slot s holds channel c(s) = (s&3)*32 + (s>>2)
__device__ __align__(16) __half d_f1t[(size_t)HWF * CCH];
// g[n] = M * r0[n] + u, stored slot-permuted to match d_f1t
__device__ __align__(16) float d_g[20000 * CCH];

// packed fp32x2 FMA (Blackwell)
#define FMA_F32X2(d, a, b, c) \
    asm("fma.rn.f32x2 %0, %1, %2, %3;" : "=l"(d) : "l"(a), "l"(b), "l"(c))

__device__ __forceinline__ unsigned long long pack_f32x2(float lo, float hi) {
    unsigned long long r;
    unsigned ulo = __float_as_uint(lo), uhi = __float_as_uint(hi);
    asm("mov.b64 %0, {%1, %2};" : "=l"(r) : "r"(ulo), "r"(uhi));
    return r;
}
__device__ __forceinline__ void unpack_f32x2(unsigned long long v, float& lo, float& hi) {
    unsigned ulo, uhi;
    asm("mov.b64 {%0, %1}, %2;" : "=r"(ulo), "=r"(uhi) : "l"(v));
    lo = __uint_as_float(ulo);
    hi = __uint_as_float(uhi);
}

// ---------------------------------------------------------------------------
// Kernel A: blocks [0,NTPB): lane=pixel-pair register transpose f1 -> d_f1t.
//           blocks [NTPB, NTPB+128): precompute M (fp16) and u.
__global__ void __launch_bounds__(256)
transpose_f1(const float* __restrict__ f1,
             const float* __restrict__ W, const float* __restrict__ b)
{
    __shared__ float wcol[CCH];
    const int blk = blockIdx.x;
    const int t = threadIdx.x;
    const int w = t >> 5, l = t & 31;

    if (blk >= NTPB) {
        // ---- precompute role: row o of M = W^T W, u[o] ----
        const int o = blk - NTPB;
        if (t < CCH) wcol[t] = W[t * CCH + o];
        __syncthreads();
        if (t < CCH) {
            float acc = 0.f;
#pragma unroll 8
            for (int k = 0; k < CCH; k++) acc += wcol[k] * W[k * CCH + t];
            d_Mh[o * CCH + t] = __float2half(acc);
            if (t == 0) {
                float uu = 0.f;
                for (int k = 0; k < CCH; k++) uu += wcol[k] * b[k];
                d_u[o] = uu;
            }
        }
        return;
    }

    // ---- transpose role: 64 pixels per block; lane = 2 pixels, warp = 16 slots ----
    const int p0 = blk * 64 + 2 * l;   // this lane's pixel pair
    float2 v[16];                      // v[d] = slot 16w+d = channel 4w+(d>>2)+32(d&3)
#pragma unroll
    for (int d = 0; d < 16; d++) {
        const int c = 4 * w + (d >> 2) + 32 * (d & 3);
        v[d] = __ldg((const float2*)(f1 + (size_t)c * HWF + p0));
    }
#pragma unroll
    for (int j2 = 0; j2 < 2; j2++) {
        unsigned q[8];
#pragma unroll
        for (int d = 0; d < 8; d++) {
            const float a = j2 ? v[2 * d].y     : v[2 * d].x;
            const float bq = j2 ? v[2 * d + 1].y : v[2 * d + 1].x;
            __half2 h = __floats2half2_rn(a, bq);
            q[d] = *reinterpret_cast<unsigned*>(&h);
        }
        __half* dst = d_f1t + (size_t)(p0 + j2) * CCH + 16 * w;
        *reinterpret_cast<uint4*>(dst)     = make_uint4(q[0], q[1], q[2], q[3]);
        *reinterpret_cast<uint4*>(dst + 8) = make_uint4(q[4], q[5], q[6], q[7]);
    }
}

// ---------------------------------------------------------------------------
// Kernel B: g[n] = M * r0[n] + u. 48 points/block in 3 batches of 16,
// double-buffered r0p: prefetch batch b+1 (LDG->regs) before matvec of batch b,
// store after, one barrier per batch. fp16 M. ~50.7 KB smem -> 3 CTAs/SM.
// smem bytes: Msh half[16384]      @0     (32768)
//             r0p float[2][128*18] @32768 (18432)   pitch 18: 8B-aligned u64 rows
//             ush float[128]       @51200 (512)
//             hi  int[48]          @51712 (192)
#define R0PITCH 18
#define G_SMEM 51904
__global__ void __launch_bounds__(256, 3)
g_kernel(const float* __restrict__ mk0, const float* __restrict__ f0,
         const int* __restrict__ stride_ptr, int N)
{
    extern __shared__ char smraw[];
    __half* Msh = (__half*)smraw;
    float*  r0p0 = (float*)(smraw + 32768);
    float*  r0p1 = (float*)(smraw + 32768 + 9216);
    float*  ush = (float*)(smraw + 51200);
    int*    hi  = (int*)(smraw + 51712);

    const int t = threadIdx.x;
    const int stride = stride_ptr ? __ldg(stride_ptr) : 8;
    const int fr = stride >> 1;
    const int n0blk = blockIdx.x * PPB;

    // header: 48 points
    if (t < PPB) {
        int n = n0blk + t;
        int nc = n < N ? n : N - 1;
        float m0x = mk0[2 * nc], m0y = mk0[2 * nc + 1];
        int cx0 = (int)(m0x * (float)fr), cy0 = (int)(m0y * (float)fr);
        int cx0c = min(max(cx0, 2), WF - 3), cy0c = min(max(cy0, 2), HF - 3);
        hi[t] = cy0c * WF + cx0c;
    }
    if (t < CCH) ush[t] = d_u[t];

    const int o    = t & 127;
    const int half = t >> 7;
    const float* fp = f0 + (size_t)o * HWF;

    {   // stage fp16 M (uint4)
        const uint4* Ms = (const uint4*)d_Mh;
        uint4* Md = (uint4*)Msh;
#pragma unroll
        for (int i = 0; i < 8; i++) Md[i * 256 + t] = __ldg(&Ms[i * 256 + t]);
    }
    __syncthreads();

    // prologue: gather batch 0 into buffer 0
#pragma unroll
    for (int k = 0; k < 8; k++) {
        const int q = half * 8 + k;
        r0p0[o * R0PITCH + q] = __ldg(fp + hi[q]);
    }
    __syncthreads();

    const int s = (o & 31) * 4 + (o >> 5);   // slot for channel o
    const float uo = ush[o];

#pragma unroll
    for (int bb = 0; bb < 3; bb++) {
        float* rbuf = (bb & 1) ? r0p1 : r0p0;
        float* wbuf = (bb & 1) ? r0p0 : r0p1;

        // prefetch next batch (LDGs issue before the matvec consumes rbuf)
        float pf[8];
        if (bb < 2) {
#pragma unroll
            for (int k = 0; k < 8; k++)
                pf[k] = __ldg(fp + hi[(bb + 1) * 16 + half * 8 + k]);
        }

        // matvec: 8 points for this half via 4 packed f32x2 accumulators
        unsigned long long a0 = pack_f32x2(uo, uo);
        unsigned long long a1 = a0, a2 = a0, a3 = a0;
        const int qb = half * 8;
#pragma unroll 8
        for (int c = 0; c < CCH; c++) {
            const float m = __half2float(Msh[c * CCH + o]);  // symmetric M
            const unsigned long long m2 = pack_f32x2(m, m);
            const unsigned long long* rp =
                (const unsigned long long*)&rbuf[c * R0PITCH + qb];
            FMA_F32X2(a0, m2, rp[0], a0);
            FMA_F32X2(a1, m2, rp[1], a1);
            FMA_F32X2(a2, m2, rp[2], a2);
            FMA_F32X2(a3, m2, rp[3], a3);
        }
        float g[8];
        unpack_f32x2(a0, g[0], g[1]);
        unpack_f32x2(a1, g[2], g[3]);
        unpack_f32x2(a2, g[4], g[5]);
        unpack_f32x2(a3, g[6], g[7]);
#pragma unroll
        for (int k = 0; k < 8; k++) {
            const int n = n0blk + bb * 16 + qb + k;
            if (n < N) d_g[(size_t)n * CCH + s] = g[k];
        }

        // store prefetched batch into the other buffer, then barrier
        if (bb < 2) {
#pragma unroll
            for (int k = 0; k < 8; k++)
                wbuf[o * R0PITCH + half * 8 + k] = pf[k];
        }
        __syncthreads();
    }
}

// ---------------------------------------------------------------------------
// Kernel C: one warp per point: correlation (fp16 f1t) + softmax + outputs.
__global__ void __launch_bounds__(256)
corr_kernel(const float* __restrict__ mk0, const float* __restrict__ mk1,
            const int* __restrict__ stride_ptr, float* __restrict__ out, int N)
{
    const int wid = threadIdx.x >> 5, lane = threadIdx.x & 31;
    const int n = blockIdx.x * 8 + wid;
    if (n >= N) return;

    const int stride = stride_ptr ? __ldg(stride_ptr) : 8;
    const int fr = stride >> 1;
    const float scalef = (float)(stride / fr);
    const float halfstr = (float)(stride >> 1);

    const float m0x = __ldg(&mk0[2 * n]), m0y = __ldg(&mk0[2 * n + 1]);
    const float m1x = __ldg(&mk1[2 * n]), m1y = __ldg(&mk1[2 * n + 1]);
    const int cx0 = (int)(m0x * (float)fr), cy0 = (int)(m0y * (float)fr);
    const int cx1 = (int)(m1x * (float)fr), cy1 = (int)(m1y * (float)fr);
    const bool valid = cx0 >= 2 && cx0 + 2 < WF && cy0 >= 2 && cy0 + 2 < HF &&
                       cx1 >= 2 && cx1 + 2 < WF && cy1 >= 2 && cy1 + 2 < HF;
    const int cx1c = min(max(cx1, 2), WF - 3);
    const int cy1c = min(max(cy1, 2), HF - 3);
    const size_t pixb = (size_t)cy1c * WF + cx1c;

    // slots 4*lane..4*lane+3 (d_g written with matching permutation)
    const float4 g4 = *(const float4*)&d_g[(size_t)n * CCH + lane * 4];

    float corr = -FLT_MAX;   // lane p (p<25) ends up holding corr[p]
#pragma unroll
    for (int row = 0; row < 5; row++) {
        const size_t rb = (pixb + (size_t)(row - 2) * WF - 2) * CCH + lane * 4;
        float r[5];
#pragma unroll
        for (int col = 0; col < 5; col++) {
            uint2 u = __ldg((const uint2*)(d_f1t + rb + (size_t)col * CCH));
            __half2 h0 = *reinterpret_cast<__half2*>(&u.x);
            __half2 h1 = *reinterpret_cast<__half2*>(&u.y);
            float2 f01 = __half22float2(h0);
            float2 f23 = __half22float2(h1);
            r[col] = g4.x * f01.x + g4.y * f01.y + g4.z * f23.x + g4.w * f23.y;
        }
#pragma unroll
        for (int d = 16; d; d >>= 1) {
            r[0] += __shfl_xor_sync(0xffffffffu, r[0], d);
            r[1] += __shfl_xor_sync(0xffffffffu, r[1], d);
            r[2] += __shfl_xor_sync(0xffffffffu, r[2], d);
            r[3] += __shfl_xor_sync(0xffffffffu, r[3], d);
            r[4] += __shfl_xor_sync(0xffffffffu, r[4], d);
        }
        const int p0 = row * 5;
#pragma unroll
        for (int col = 0; col < 5; col++)
            if (lane == p0 + col) corr = r[col];
    }

    // softmax over lanes 0..24 + expectation (per-point constant cancels)
    const bool inpatch = lane < 25;
    const int dx = lane % 5 - 2;
    const int dy = lane / 5 - 2;
    float cm = corr;
#pragma unroll
    for (int d = 16; d; d >>= 1)
        cm = fmaxf(cm, __shfl_xor_sync(0xffffffffu, cm, d));
    float e  = inpatch ? __expf(corr - cm) : 0.f;
    float ex = e * (float)dx;
    float ey = e * (float)dy;
    float s  = e;
#pragma unroll
    for (int d = 16; d; d >>= 1) {
        s  += __shfl_xor_sync(0xffffffffu, s,  d);
        ex += __shfl_xor_sync(0xffffffffu, ex, d);
        ey += __shfl_xor_sync(0xffffffffu, ey, d);
    }
    if (lane == 0) {
        out[2 * n]     = m0x * (float)stride + halfstr;
        out[2 * n + 1] = m0y * (float)stride + halfstr;
        const float inv = scalef / s;
        const float ox = valid ? ex * inv : 0.f;
        const float oy = valid ? ey * inv : 0.f;
        out[2 * N + 2 * n]     = m1x * (float)stride + halfstr + ox;
        out[2 * N + 2 * n + 1] = m1y * (float)stride + halfstr + oy;
    }
}

// ---------------------------------------------------------------------------
extern "C" void kernel_launch(void* const* d_in, const int* in_sizes, int n_in,
                              void* d_out, int out_size) {
    const float* mk0 = (const float*)d_in[0];
    const float* mk1 = (const float*)d_in[1];
    const float* f0  = (const float*)d_in[2];
    const float* f1  = (const float*)d_in[3];
    const float* pw  = (const float*)d_in[4];
    const float* pb  = (const float*)d_in[5];
    const int* stridep = (n_in >= 7) ? (const int*)d_in[6] : nullptr;
    float* out = (float*)d_out;

    int N = in_sizes[0] / 2;

    transpose_f1<<<NTPB + 128, 256>>>(f1, pw, pb);

    cudaFuncSetAttribute(g_kernel,
                         cudaFuncAttributeMaxDynamicSharedMemorySize, G_SMEM);
    g_kernel<<<(N + PPB - 1) / PPB, 256, G_SMEM>>>(mk0, f0, stridep, N);

    corr_kernel<<<(N + 7) / 8, 256>>>(mk0, mk1, stridep, out, N);
}

// round 13
// speedup vs baseline: 1.4713x; 1.0346x over previous
#include <cuda_runtime.h>
#include <cuda_fp16.h>
#include <float.h>
#include <math.h>

#define CCH 128
#define HWF 409600   // 640*640
#define WF 640
#define HF 640
#define NTPB (HWF / 64)   // 6400 transpose blocks (64 pixels each)
#define PPB 48            // points per matvec block (3 batches of 16)
#define NMAX 20000

// Slot permutation: slot s holds channel c(s) = (s&3)*32 + (s>>2); s(o) = 4*(o&31)+(o>>5)
// Msp[s_in*128 + s_out] = M[c(s_in)][c(s_out)] fp16; up[s] = u[c(s)]
__device__ __align__(16) __half d_Msp[CCH * CCH];
__device__ __align__(16) float  d_up[CCH];
// Transposed f1 in fp16: [H*W][128 slots]
__device__ __align__(16) __half d_f1t[(size_t)HWF * CCH];
// Dense gathered center features, slot order: d_r0[n*128 + s]
__device__ __align__(16) float d_r0[NMAX * CCH];
// g[n] = M * r0[n] + u, slot order
__device__ __align__(16) float d_g[NMAX * CCH];

// packed fp32x2 FMA (Blackwell)
#define FMA_F32X2(d, a, b, c) \
    asm("fma.rn.f32x2 %0, %1, %2, %3;" : "=l"(d) : "l"(a), "l"(b), "l"(c))

__device__ __forceinline__ unsigned long long pack_f32x2(float lo, float hi) {
    unsigned long long r;
    unsigned ulo = __float_as_uint(lo), uhi = __float_as_uint(hi);
    asm("mov.b64 %0, {%1, %2};" : "=l"(r) : "r"(ulo), "r"(uhi));
    return r;
}
__device__ __forceinline__ void unpack_f32x2(unsigned long long v, float& lo, float& hi) {
    unsigned ulo, uhi;
    asm("mov.b64 {%0, %1}, %2;" : "=r"(ulo), "=r"(uhi) : "l"(v));
    lo = __uint_as_float(ulo);
    hi = __uint_as_float(uhi);
}

// ---------------------------------------------------------------------------
// Kernel 1 "prep": three roles by block index.
//   blk <  128                : precompute Msp (fp16, slot-permuted) + up
//   else r=blk-128, sub=r%7   : sub<5 -> transpose tile grp*5+sub
//                               sub>=5 -> gather 8 points gidx=grp*2+(sub-5)
__global__ void __launch_bounds__(256)
prep_kernel(const float* __restrict__ f1,
            const float* __restrict__ W, const float* __restrict__ b,
            const float* __restrict__ mk0, const float* __restrict__ f0,
            const int* __restrict__ stride_ptr, int N)
{
    __shared__ float wcol[CCH];
    const int blk = blockIdx.x;
    const int t = threadIdx.x;
    const int w = t >> 5, l = t & 31;

    if (blk < 128) {
        // ---- precompute role: row o of M = W^T W, slot-permuted store ----
        const int o = blk;
        if (t < CCH) wcol[t] = W[t * CCH + o];
        __syncthreads();
        if (t < CCH) {
            float acc = 0.f;
#pragma unroll 8
            for (int k = 0; k < CCH; k++) acc += wcol[k] * W[k * CCH + t];
            const int so = 4 * (o & 31) + (o >> 5);
            const int st = 4 * (t & 31) + (t >> 5);
            d_Msp[so * CCH + st] = __float2half(acc);   // symmetric
            if (t == 0) {
                float uu = 0.f;
                for (int k = 0; k < CCH; k++) uu += wcol[k] * b[k];
                d_up[so] = uu;
            }
        }
        return;
    }

    const int r = blk - 128;
    const int grp = r / 7, sub = r % 7;

    if (sub < 5) {
        // ---- transpose role: 64 pixels; lane = 2 pixels, warp = 16 slots ----
        const int tidx = grp * 5 + sub;
        if (tidx >= NTPB) return;
        const int p0 = tidx * 64 + 2 * l;
        float2 v[16];                  // v[d] = slot 16w+d = channel 4w+(d>>2)+32(d&3)
#pragma unroll
        for (int d = 0; d < 16; d++) {
            const int c = 4 * w + (d >> 2) + 32 * (d & 3);
            v[d] = __ldg((const float2*)(f1 + (size_t)c * HWF + p0));
        }
#pragma unroll
        for (int j2 = 0; j2 < 2; j2++) {
            unsigned q[8];
#pragma unroll
            for (int d = 0; d < 8; d++) {
                const float a  = j2 ? v[2 * d].y     : v[2 * d].x;
                const float bq = j2 ? v[2 * d + 1].y : v[2 * d + 1].x;
                __half2 h = __floats2half2_rn(a, bq);
                q[d] = *reinterpret_cast<unsigned*>(&h);
            }
            __half* dst = d_f1t + (size_t)(p0 + j2) * CCH + 16 * w;
            *reinterpret_cast<uint4*>(dst)     = make_uint4(q[0], q[1], q[2], q[3]);
            *reinterpret_cast<uint4*>(dst + 8) = make_uint4(q[4], q[5], q[6], q[7]);
        }
        return;
    }

    // ---- gather role: 8 points (one per warp), lane loads 4 channels ----
    {
        const int gidx = grp * 2 + (sub - 5);
        const int n = gidx * 8 + w;
        if (n >= N) return;
        const int stride = stride_ptr ? __ldg(stride_ptr) : 8;
        const int fr = stride >> 1;
        const float m0x = __ldg(&mk0[2 * n]), m0y = __ldg(&mk0[2 * n + 1]);
        const int cx0 = (int)(m0x * (float)fr), cy0 = (int)(m0y * (float)fr);
        const int cx0c = min(max(cx0, 2), WF - 3), cy0c = min(max(cy0, 2), HF - 3);
        const int pix0 = cy0c * WF + cx0c;
        float v0 = __ldg(f0 + (size_t)(l      ) * HWF + pix0);
        float v1 = __ldg(f0 + (size_t)(l + 32 ) * HWF + pix0);
        float v2 = __ldg(f0 + (size_t)(l + 64 ) * HWF + pix0);
        float v3 = __ldg(f0 + (size_t)(l + 96 ) * HWF + pix0);
        // slot s = 4l+k holds channel k*32+l  ✓
        *(float4*)&d_r0[(size_t)n * CCH + 4 * l] = make_float4(v0, v1, v2, v3);
    }
}

// ---------------------------------------------------------------------------
// Kernel 2: matvec g[n] = M*r0[n] + u, all in slot space. Dense coalesced r0.
// smem bytes: Msh half[16384]      @0     (32768)
//             r0p float[2][128*20] @32768 (20480)   pitch 20: 16B-aligned rows
//             ush float[128]       @53248 (512)
#define R0PITCH 20
#define G_SMEM 53760
__global__ void __launch_bounds__(256, 3)
matvec_kernel(int N)
{
    extern __shared__ char smraw[];
    __half* Msh  = (__half*)smraw;
    float*  r0p0 = (float*)(smraw + 32768);
    float*  r0p1 = (float*)(smraw + 32768 + 10240);
    float*  ush  = (float*)(smraw + 53248);

    const int t = threadIdx.x;
    const int n0blk = blockIdx.x * PPB;
    const int o    = t & 127;       // slot index
    const int half = t >> 7;

    {   // stage fp16 Msp (uint4) and up
        const uint4* Ms = (const uint4*)d_Msp;
        uint4* Md = (uint4*)Msh;
#pragma unroll
        for (int i = 0; i < 8; i++) Md[i * 256 + t] = __ldg(&Ms[i * 256 + t]);
        if (t < CCH) ush[t] = d_up[t];
    }

    // prologue: coalesced load of batch 0
#pragma unroll
    for (int k = 0; k < 8; k++) {
        const int q = half * 8 + k;
        const int nc = min(n0blk + q, N - 1);
        r0p0[o * R0PITCH + q] = __ldg(&d_r0[(size_t)nc * CCH + o]);
    }
    __syncthreads();

    const float uo = ush[o];

#pragma unroll
    for (int bb = 0; bb < 3; bb++) {
        float* rbuf = (bb & 1) ? r0p1 : r0p0;
        float* wbuf = (bb & 1) ? r0p0 : r0p1;

        // prefetch next batch (coalesced)
        float pf[8];
        if (bb < 2) {
#pragma unroll
            for (int k = 0; k < 8; k++) {
                const int nc = min(n0blk + (bb + 1) * 16 + half * 8 + k, N - 1);
                pf[k] = __ldg(&d_r0[(size_t)nc * CCH + o]);
            }
        }

        // matvec: 8 points for this half via 4 packed f32x2 accumulators
        unsigned long long a0 = pack_f32x2(uo, uo);
        unsigned long long a1 = a0, a2 = a0, a3 = a0;
        const int qb = half * 8;
#pragma unroll 8
        for (int c = 0; c < CCH; c++) {
            const float m = __half2float(Msh[c * CCH + o]);   // Ms[s_in=c][s_out=o]
            const unsigned long long m2 = pack_f32x2(m, m);
            const float4* rp4 = (const float4*)&rbuf[c * R0PITCH + qb];
            const float4 rA = rp4[0], rB = rp4[1];
            FMA_F32X2(a0, m2, pack_f32x2(rA.x, rA.y), a0);
            FMA_F32X2(a1, m2, pack_f32x2(rA.z, rA.w), a1);
            FMA_F32X2(a2, m2, pack_f32x2(rB.x, rB.y), a2);
            FMA_F32X2(a3, m2, pack_f32x2(rB.z, rB.w), a3);
        }
        float g[8];
        unpack_f32x2(a0, g[0], g[1]);
        unpack_f32x2(a1, g[2], g[3]);
        unpack_f32x2(a2, g[4], g[5]);
        unpack_f32x2(a3, g[6], g[7]);
#pragma unroll
        for (int k = 0; k < 8; k++) {
            const int n = n0blk + bb * 16 + qb + k;
            if (n < N) d_g[(size_t)n * CCH + o] = g[k];
        }

        if (bb < 2) {
#pragma unroll
            for (int k = 0; k < 8; k++)
                wbuf[o * R0PITCH + half * 8 + k] = pf[k];
        }
        __syncthreads();
    }
}

// ---------------------------------------------------------------------------
// Kernel 3: one warp per point: correlation (fp16 f1t) + softmax + outputs.
__global__ void __launch_bounds__(256)
corr_kernel(const float* __restrict__ mk0, const float* __restrict__ mk1,
            const int* __restrict__ stride_ptr, float* __restrict__ out, int N)
{
    const int wid = threadIdx.x >> 5, lane = threadIdx.x & 31;
    const int n = blockIdx.x * 8 + wid;
    if (n >= N) return;

    const int stride = stride_ptr ? __ldg(stride_ptr) : 8;
    const int fr = stride >> 1;
    const float scalef = (float)(stride / fr);
    const float halfstr = (float)(stride >> 1);

    const float m0x = __ldg(&mk0[2 * n]), m0y = __ldg(&mk0[2 * n + 1]);
    const float m1x = __ldg(&mk1[2 * n]), m1y = __ldg(&mk1[2 * n + 1]);
    const int cx0 = (int)(m0x * (float)fr), cy0 = (int)(m0y * (float)fr);
    const int cx1 = (int)(m1x * (float)fr), cy1 = (int)(m1y * (float)fr);
    const bool valid = cx0 >= 2 && cx0 + 2 < WF && cy0 >= 2 && cy0 + 2 < HF &&
                       cx1 >= 2 && cx1 + 2 < WF && cy1 >= 2 && cy1 + 2 < HF;
    const int cx1c = min(max(cx1, 2), WF - 3);
    const int cy1c = min(max(cy1, 2), HF - 3);
    const size_t pixb = (size_t)cy1c * WF + cx1c;

    // slots 4*lane..4*lane+3
    const float4 g4 = *(const float4*)&d_g[(size_t)n * CCH + lane * 4];

    float corr = -FLT_MAX;   // lane p (p<25) ends up holding corr[p]
#pragma unroll
    for (int row = 0; row < 5; row++) {
        const size_t rb = (pixb + (size_t)(row - 2) * WF - 2) * CCH + lane * 4;
        float r[5];
#pragma unroll
        for (int col = 0; col < 5; col++) {
            uint2 u = __ldg((const uint2*)(d_f1t + rb + (size_t)col * CCH));
            __half2 h0 = *reinterpret_cast<__half2*>(&u.x);
            __half2 h1 = *reinterpret_cast<__half2*>(&u.y);
            float2 f01 = __half22float2(h0);
            float2 f23 = __half22float2(h1);
            r[col] = g4.x * f01.x + g4.y * f01.y + g4.z * f23.x + g4.w * f23.y;
        }
#pragma unroll
        for (int d = 16; d; d >>= 1) {
            r[0] += __shfl_xor_sync(0xffffffffu, r[0], d);
            r[1] += __shfl_xor_sync(0xffffffffu, r[1], d);
            r[2] += __shfl_xor_sync(0xffffffffu, r[2], d);
            r[3] += __shfl_xor_sync(0xffffffffu, r[3], d);
            r[4] += __shfl_xor_sync(0xffffffffu, r[4], d);
        }
        const int p0 = row * 5;
#pragma unroll
        for (int col = 0; col < 5; col++)
            if (lane == p0 + col) corr = r[col];
    }

    // softmax over lanes 0..24 + expectation (per-point constant cancels)
    const bool inpatch = lane < 25;
    const int dx = lane % 5 - 2;
    const int dy = lane / 5 - 2;
    float cm = corr;
#pragma unroll
    for (int d = 16; d; d >>= 1)
        cm = fmaxf(cm, __shfl_xor_sync(0xffffffffu, cm, d));
    float e  = inpatch ? __expf(corr - cm) : 0.f;
    float ex = e * (float)dx;
    float ey = e * (float)dy;
    float s  = e;
#pragma unroll
    for (int d = 16; d; d >>= 1) {
        s  += __shfl_xor_sync(0xffffffffu, s,  d);
        ex += __shfl_xor_sync(0xffffffffu, ex, d);
        ey += __shfl_xor_sync(0xffffffffu, ey, d);
    }
    if (lane == 0) {
        out[2 * n]     = m0x * (float)stride + halfstr;
        out[2 * n + 1] = m0y * (float)stride + halfstr;
        const float inv = scalef / s;
        const float ox = valid ? ex * inv : 0.f;
        const float oy = valid ? ey * inv : 0.f;
        out[2 * N + 2 * n]     = m1x * (float)stride + halfstr + ox;
        out[2 * N + 2 * n + 1] = m1y * (float)stride + halfstr + oy;
    }
}

// ---------------------------------------------------------------------------
extern "C" void kernel_launch(void* const* d_in, const int* in_sizes, int n_in,
                              void* d_out, int out_size) {
    const float* mk0 = (const float*)d_in[0];
    const float* mk1 = (const float*)d_in[1];
    const float* f0  = (const float*)d_in[2];
    const float* f1  = (const float*)d_in[3];
    const float* pw  = (const float*)d_in[4];
    const float* pb  = (const float*)d_in[5];
    const int* stridep = (n_in >= 7) ? (const int*)d_in[6] : nullptr;
    float* out = (float*)d_out;

    int N = in_sizes[0] / 2;

    // prep grid: 128 precompute + interleaved 5:2 transpose/gather groups
    int ngather = (N + 15) / 16;                 // gather blocks (8 pts each), /2 per group
    int grpsT = (NTPB + 4) / 5;                  // 1280
    int grpsG = (ngather + 1) / 2;
    int grps = grpsT > grpsG ? grpsT : grpsG;
    prep_kernel<<<128 + grps * 7, 256>>>(f1, pw, pb, mk0, f0, stridep, N);

    cudaFuncSetAttribute(matvec_kernel,
                         cudaFuncAttributeMaxDynamicSharedMemorySize, G_SMEM);
    matvec_kernel<<<(N + PPB - 1) / PPB, 256, G_SMEM>>>(N);

    corr_kernel<<<(N + 7) / 8, 256>>>(mk0, mk1, stridep, out, N);
}